// round 8
// baseline (speedup 1.0000x reference)
#include <cuda_runtime.h>
#include <cstdint>
#include <math.h>

#define DM   1024
#define NEXP 32
#define FE   128
#define TT   4
#define BATCH 4
#define SEQ  4096
#define NTOK (BATCH*SEQ)   // 16384
#define NGRP (SEQ/TT)      // 1024

typedef unsigned long long ull;

// scratch (device globals; no allocation)
__device__ float g_logitsT[BATCH*TT*NEXP*NGRP];   // 2MB [(b*4+t)*32+e][g]
__device__ int   g_selg[BATCH*TT*NEXP];
__device__ float g_selp[BATCH*TT*NEXP];

__device__ __forceinline__ ull pack2(float a, float b) {
    ull r; asm("mov.b64 %0,{%1,%2};" : "=l"(r) : "f"(a), "f"(b)); return r;
}
__device__ __forceinline__ void unpack2(ull v, float& a, float& b) {
    asm("mov.b64 {%0,%1},%2;" : "=f"(a), "=f"(b) : "l"(v));
}
__device__ __forceinline__ void ffma2(ull& d, ull a, ull b) {
    asm("fma.rn.f32x2 %0,%1,%2,%0;" : "+l"(d) : "l"(a), "l"(b));
}

// ---------------------------------------------------------------------------
// K1: zero output + logits GEMM. 128 blocks x 512 threads.
// warp = (eq, ks). Thread tile: 4 tok x 8 exp. x staged transposed [k][tok]
// pad-129 (conflict-free STS and LDS). Depth-2 register prefetch: at chunk c
// LDG chunk c+2, STS chunk c+1 (loaded one full chunk earlier), compute c.
// ---------------------------------------------------------------------------
#define XKROW 129
#define XKBUF (32*XKROW)                        // floats per buffer
#define SMEM1 (131072 + 2*XKBUF*4)              // 164096

__global__ void __launch_bounds__(512, 1)
k_logits(const float* __restrict__ x, const float* __restrict__ ctrl,
         float* __restrict__ out)
{
    extern __shared__ char smraw[];
    ull*   ctrl_s = reinterpret_cast<ull*>(smraw);              // [1024k][16 ull]
    float* xk0    = reinterpret_cast<float*>(smraw + 131072);   // [32][129]
    float* xk1    = xk0 + XKBUF;

    const int tid = threadIdx.x;
    const int tg  = tid & 31;
    const int w   = tid >> 5;
    const int eq  = w >> 2;          // expert quarter
    const int ks  = w & 3;           // k slice (8 k of 32-k chunk)
    const int tb  = blockIdx.x;
    const float* xblk = x + (size_t)tb * 128 * DM;

    // fire-and-forget zero of this block's output slab
    {
        float4 z = make_float4(0.f, 0.f, 0.f, 0.f);
        float4* op = reinterpret_cast<float4*>(out) + (size_t)tb * 32768;
        #pragma unroll
        for (int i = 0; i < 64; i++) op[tid + i*512] = z;
    }

    // staging geometry
    const int s_tok0 = tid >> 3;
    const int s_kq   = tid & 7;
    const float* sbase = xblk + (size_t)s_tok0*DM + s_kq*4;
    const float* sbase2 = sbase + (size_t)64*DM;

    float4 Ra0, Ra1, Rb0, Rb1;

    // prologue: chunk0 -> buf0 ; chunk1 -> regs B
    Ra0 = *reinterpret_cast<const float4*>(sbase);
    Ra1 = *reinterpret_cast<const float4*>(sbase2);

    // load full controller into smem
    {
        const float4* cg4 = reinterpret_cast<const float4*>(ctrl);
        float4* cs4 = reinterpret_cast<float4*>(ctrl_s);
        #pragma unroll
        for (int i = 0; i < 16; i++) cs4[tid + i*512] = cg4[tid + i*512];
    }
    {
        const float* p0 = reinterpret_cast<const float*>(&Ra0);
        const float* p1 = reinterpret_cast<const float*>(&Ra1);
        #pragma unroll
        for (int j = 0; j < 4; j++) {
            xk0[(s_kq*4 + j)*XKROW + s_tok0]      = p0[j];
            xk0[(s_kq*4 + j)*XKROW + s_tok0 + 64] = p1[j];
        }
    }
    Rb0 = *reinterpret_cast<const float4*>(sbase  + 32);
    Rb1 = *reinterpret_cast<const float4*>(sbase2 + 32);
    __syncthreads();

    ull acc[4][4];
    #pragma unroll
    for (int i = 0; i < 4; i++)
        #pragma unroll
        for (int p = 0; p < 4; p++) acc[i][p] = 0ull;

    for (int c = 0; c < 32; c++) {
        // 1) issue LDG for chunk c+2 into reg set (c&1 ? B : A)... invariant:
        //    reg set R[(c+1)&1] currently holds chunk c+1; load into R[c&1].
        if (c < 30) {
            if ((c & 1) == 0) {
                Ra0 = *reinterpret_cast<const float4*>(sbase  + (c+2)*32);
                Ra1 = *reinterpret_cast<const float4*>(sbase2 + (c+2)*32);
            } else {
                Rb0 = *reinterpret_cast<const float4*>(sbase  + (c+2)*32);
                Rb1 = *reinterpret_cast<const float4*>(sbase2 + (c+2)*32);
            }
        }
        // 2) STS chunk c+1 (in R[(c+1)&1]) into buf[(c+1)&1]
        if (c < 31) {
            float* bw = ((c+1) & 1) ? xk1 : xk0;
            const float4& q0 = ((c+1) & 1) ? Rb0 : Ra0;
            const float4& q1 = ((c+1) & 1) ? Rb1 : Ra1;
            const float* p0 = reinterpret_cast<const float*>(&q0);
            const float* p1 = reinterpret_cast<const float*>(&q1);
            #pragma unroll
            for (int j = 0; j < 4; j++) {
                bw[(s_kq*4 + j)*XKROW + s_tok0]      = p0[j];
                bw[(s_kq*4 + j)*XKROW + s_tok0 + 64] = p1[j];
            }
        }
        // 3) compute chunk c
        const float* xb = (c & 1) ? xk1 : xk0;
        #pragma unroll
        for (int u = 0; u < 8; u++) {
            const ulonglong2* cb = reinterpret_cast<const ulonglong2*>(
                ctrl_s + (size_t)(c*32 + ks*8 + u)*16 + eq*4);
            ulonglong2 q0 = cb[0], q1 = cb[1];
            ull cu0 = q0.x, cu1 = q0.y, cu2 = q1.x, cu3 = q1.y;
            const float* xrow = xb + (ks*8 + u)*XKROW + tg;
            #pragma unroll
            for (int i = 0; i < 4; i++) {
                float xf = xrow[32*i];
                ull x2 = pack2(xf, xf);
                ffma2(acc[i][0], x2, cu0);
                ffma2(acc[i][1], x2, cu1);
                ffma2(acc[i][2], x2, cu2);
                ffma2(acc[i][3], x2, cu3);
            }
        }
        __syncthreads();
    }

    // reduce over 4 k-slices via smem (reuse ctrl_s)
    ull* red = ctrl_s;
    #pragma unroll
    for (int i = 0; i < 4; i++)
        #pragma unroll
        for (int p = 0; p < 4; p++)
            red[(((size_t)(eq*4 + ks)*128) + (tg + 32*i))*4 + p] = acc[i][p];
    __syncthreads();

    #pragma unroll
    for (int j = 0; j < 4; j++) {
        int s = tid*4 + j;               // item = (tok, expert-pair)
        int tok = s >> 4, pr = s & 15;
        int peq = pr >> 2, pp = pr & 3;
        float lo = 0.f, hi = 0.f;
        #pragma unroll
        for (int k2 = 0; k2 < 4; k2++) {
            float a, b;
            unpack2(red[(((size_t)(peq*4 + k2)*128) + tok)*4 + pp], a, b);
            lo += a; hi += b;
        }
        int gt = tb*128 + tok;
        int b  = gt >> 12;
        int sg = gt & 4095;
        int g  = sg >> 2, t = sg & 3;
        float tbk = (float)t * (1e-6f / 3.0f);   // linspace(0,1e-6,4)[t]
        int row = (b*4 + t)*32 + 2*pr;
        g_logitsT[(size_t)row*1024 + g]     = lo + tbk;
        g_logitsT[(size_t)(row+1)*1024 + g] = hi + tbk;
    }
}

// ---------------------------------------------------------------------------
// K_sel: one block per (b,t,e) row: argmax + softmax denominator over 1024 g.
// ---------------------------------------------------------------------------
__global__ void __launch_bounds__(256, 8)
k_sel()
{
    __shared__ float rm[8];
    __shared__ int   rmi[8];
    __shared__ float rs[8];
    __shared__ float mfin;

    const int tid  = threadIdx.x;
    const int lane = tid & 31;
    const int wp   = tid >> 5;
    const float* L = g_logitsT + ((size_t)blockIdx.x << 10);

    float m = -3.4e38f; int mi = 0;
    #pragma unroll
    for (int j = 0; j < 4; j++) {
        int i = tid + j*256;
        float v = L[i];
        if (v > m) { m = v; mi = i; }
    }
    #pragma unroll
    for (int o = 16; o; o >>= 1) {
        float om = __shfl_down_sync(0xffffffffu, m, o);
        int   oi = __shfl_down_sync(0xffffffffu, mi, o);
        if (om > m || (om == m && oi < mi)) { m = om; mi = oi; }
    }
    if (lane == 0) { rm[wp] = m; rmi[wp] = mi; }
    __syncthreads();
    if (tid == 0) {
        #pragma unroll
        for (int w = 1; w < 8; w++) {
            if (rm[w] > m || (rm[w] == m && rmi[w] < mi)) { m = rm[w]; mi = rmi[w]; }
        }
        g_selg[blockIdx.x] = mi;
        mfin = m;
    }
    __syncthreads();
    m = mfin;

    float s = 0.f;
    #pragma unroll
    for (int j = 0; j < 4; j++) s += expf(L[tid + j*256] - m);
    #pragma unroll
    for (int o = 16; o; o >>= 1) s += __shfl_down_sync(0xffffffffu, s, o);
    if (lane == 0) rs[wp] = s;
    __syncthreads();
    if (tid == 0) {
        float tot = 0.f;
        #pragma unroll
        for (int w = 0; w < 8; w++) tot += rs[w];
        g_selp[blockIdx.x] = 1.0f / tot;
    }
}

// ---------------------------------------------------------------------------
// K2: up-proj + down-proj + scatter-add, split over 2 f-halves.
// grid 256 = (b, e, fs) x 256 threads; 64 f per block.
// ---------------------------------------------------------------------------
__global__ void __launch_bounds__(256, 2)
k_expert(const float* __restrict__ x, const float* __restrict__ f1,
         const float* __restrict__ bias, const float* __restrict__ f2,
         float* __restrict__ out)
{
    __shared__ float xs[4][DM];          // 16KB
    __shared__ float part[8][4][64];     // 8KB
    __shared__ float avs[4][64];
    __shared__ float Wsm[4][64];
    __shared__ int   sg[4];
    __shared__ float sp[4];

    const int tid  = threadIdx.x;
    const int lane = tid & 31;
    const int b  = blockIdx.x >> 6;
    const int e  = (blockIdx.x >> 1) & 31;
    const int fs = blockIdx.x & 1;

    if (tid < 4) {
        sg[tid] = g_selg[(b*4 + tid)*32 + e];
        sp[tid] = g_selp[(b*4 + tid)*32 + e];
    }
    __syncthreads();

    // --- load the 4 selected token rows into smem ---
    {
        const int ts = tid >> 6;
        const int gt = tid & 63;
        const float* xr = x + ((size_t)b*SEQ + sg[ts]*4 + ts) * DM;
        float4* dst = reinterpret_cast<float4*>(xs[ts]);
        const float4* src = reinterpret_cast<const float4*>(xr);
        #pragma unroll
        for (int i = 0; i < 4; i++) dst[gt + i*64] = src[gt + i*64];
    }
    __syncthreads();

    // --- up-projection: warp w owns 128 d; lane handles f = lane, lane+32 ---
    {
        const int w = tid >> 5;
        float a0[4] = {0,0,0,0};    // f = fs*64 + lane
        float a1[4] = {0,0,0,0};    // f = fs*64 + lane + 32
        const float* f1p = f1 + (size_t)(w*128)*(NEXP*FE) + e*FE + fs*64 + lane;
        const float* x0 = xs[0] + w*128;
        const float* x1 = xs[1] + w*128;
        const float* x2 = xs[2] + w*128;
        const float* x3 = xs[3] + w*128;
        #pragma unroll 8
        for (int d = 0; d < 128; d++) {
            float w0 = f1p[(size_t)d * (NEXP*FE)];
            float w1 = f1p[(size_t)d * (NEXP*FE) + 32];
            float v0 = x0[d], v1 = x1[d], v2 = x2[d], v3 = x3[d];
            a0[0] += v0*w0; a0[1] += v1*w0; a0[2] += v2*w0; a0[3] += v3*w0;
            a1[0] += v0*w1; a1[1] += v1*w1; a1[2] += v2*w1; a1[3] += v3*w1;
        }
        #pragma unroll
        for (int t = 0; t < 4; t++) {
            part[w][t][lane]      = a0[t];
            part[w][t][lane + 32] = a1[t];
        }
    }
    __syncthreads();

    {
        const int t = tid >> 6, f = tid & 63;
        float s = 0.f;
        #pragma unroll
        for (int w = 0; w < 8; w++) s += part[w][t][f];
        avs[t][f] = s;
    }
    __syncthreads();

    if (tid < 64) {
        const int f = tid;
        float av[4] = {avs[0][f], avs[1][f], avs[2][f], avs[3][f]};
        int   gg[4] = {sg[0], sg[1], sg[2], sg[3]};
        float pp[4] = {sp[0], sp[1], sp[2], sp[3]};
        float bi = bias[e*FE + fs*64 + f];
        #pragma unroll
        for (int t = 0; t < 4; t++) {
            float sum = bi;
            #pragma unroll
            for (int t2 = 0; t2 < 4; t2++)
                if (gg[t2] == gg[t]) sum += pp[t2] * av[t2];
            Wsm[t][f] = pp[t] * fmaxf(sum, 0.f);
        }
    }
    __syncthreads();

    // --- down-projection: thread owns 4 d' columns, 64 f rows ---
    {
        float o0[4] = {0,0,0,0}, o1[4] = {0,0,0,0};
        float o2[4] = {0,0,0,0}, o3[4] = {0,0,0,0};
        const float* f2p = f2 + (size_t)e*FE*DM + (size_t)(fs*64)*DM + tid*4;
        #pragma unroll 8
        for (int f = 0; f < 64; f++) {
            float4 v = *reinterpret_cast<const float4*>(f2p + (size_t)f*DM);
            float w0 = Wsm[0][f], w1 = Wsm[1][f], w2 = Wsm[2][f], w3 = Wsm[3][f];
            o0[0] += w0*v.x; o0[1] += w0*v.y; o0[2] += w0*v.z; o0[3] += w0*v.w;
            o1[0] += w1*v.x; o1[1] += w1*v.y; o1[2] += w1*v.z; o1[3] += w1*v.w;
            o2[0] += w2*v.x; o2[1] += w2*v.y; o2[2] += w2*v.z; o2[3] += w2*v.w;
            o3[0] += w3*v.x; o3[1] += w3*v.y; o3[2] += w3*v.z; o3[3] += w3*v.w;
        }
        float* ob = out + (size_t)b*SEQ*DM + tid*4;
        float* r0 = ob + (size_t)(sg[0]*4 + 0)*DM;
        float* r1 = ob + (size_t)(sg[1]*4 + 1)*DM;
        float* r2 = ob + (size_t)(sg[2]*4 + 2)*DM;
        float* r3 = ob + (size_t)(sg[3]*4 + 3)*DM;
        #pragma unroll
        for (int j = 0; j < 4; j++) atomicAdd(r0 + j, o0[j]);
        #pragma unroll
        for (int j = 0; j < 4; j++) atomicAdd(r1 + j, o1[j]);
        #pragma unroll
        for (int j = 0; j < 4; j++) atomicAdd(r2 + j, o2[j]);
        #pragma unroll
        for (int j = 0; j < 4; j++) atomicAdd(r3 + j, o3[j]);
    }
}

extern "C" void kernel_launch(void* const* d_in, const int* in_sizes, int n_in,
                              void* d_out, int out_size)
{
    const float* x    = (const float*)d_in[0];
    const float* ctrl = (const float*)d_in[1];
    const float* f1   = (const float*)d_in[2];
    const float* bias = (const float*)d_in[3];
    const float* f2   = (const float*)d_in[4];
    float* out = (float*)d_out;

    cudaFuncSetAttribute(k_logits, cudaFuncAttributeMaxDynamicSharedMemorySize, SMEM1);

    k_logits<<<128, 512, SMEM1>>>(x, ctrl, out);
    k_sel<<<BATCH*TT*NEXP, 256>>>();
    k_expert<<<BATCH*NEXP*2, 256>>>(x, f1, bias, f2, out);
}

// round 9
// speedup vs baseline: 1.1028x; 1.1028x over previous
#include <cuda_runtime.h>
#include <cstdint>
#include <math.h>

#define DM   1024
#define NEXP 32
#define FE   128
#define TT   4
#define BATCH 4
#define SEQ  4096
#define NTOK (BATCH*SEQ)   // 16384
#define NGRP (SEQ/TT)      // 1024

typedef unsigned long long ull;

// scratch (device globals; no allocation)
__device__ float g_logitsT[BATCH*TT*NEXP*NGRP];   // 2MB [(b*4+t)*32+e][g]
__device__ int   g_selg[BATCH*TT*NEXP];
__device__ float g_selp[BATCH*TT*NEXP];

__device__ __forceinline__ ull pack2(float a, float b) {
    ull r; asm("mov.b64 %0,{%1,%2};" : "=l"(r) : "f"(a), "f"(b)); return r;
}
__device__ __forceinline__ void unpack2(ull v, float& a, float& b) {
    asm("mov.b64 {%0,%1},%2;" : "=f"(a), "=f"(b) : "l"(v));
}
__device__ __forceinline__ void ffma2(ull& d, ull a, ull b) {
    asm("fma.rn.f32x2 %0,%1,%2,%0;" : "+l"(d) : "l"(a), "l"(b));
}

// ---------------------------------------------------------------------------
// K1: zero output + logits GEMM. 128 blocks x 512 threads.
// warp = (eq, ks). Thread tile: 4 tok x 8 exp. x staged in smem as DUPLICATED
// (v,v) 64-bit pairs, layout [k][tok] with ull row stride 129: STS.64 and
// LDS.64 both conflict-free, and LDS.64 results feed fma.rn.f32x2 directly
// (no pack MOVs in the inner loop). Full controller in smem.
// ---------------------------------------------------------------------------
#define XKROW_U 129                              // ull per k-row
#define XKBUF_U (32*XKROW_U)                     // ull per buffer (4128)
#define SMEM1 (131072 + 2*XKBUF_U*8)             // 197120

__global__ void __launch_bounds__(512, 1)
k_logits(const float* __restrict__ x, const float* __restrict__ ctrl,
         float* __restrict__ out)
{
    extern __shared__ char smraw[];
    ull* ctrl_s = reinterpret_cast<ull*>(smraw);              // [1024k][16 ull]
    ull* xk0    = reinterpret_cast<ull*>(smraw + 131072);     // [32][129] dup
    ull* xk1    = xk0 + XKBUF_U;

    const int tid = threadIdx.x;
    const int tg  = tid & 31;
    const int w   = tid >> 5;
    const int eq  = w >> 2;          // expert quarter
    const int ks  = w & 3;           // k slice (8 k of 32-k chunk)
    const int tb  = blockIdx.x;
    const float* xblk = x + (size_t)tb * 128 * DM;

    // fire-and-forget zero of this block's output slab
    {
        float4 z = make_float4(0.f, 0.f, 0.f, 0.f);
        float4* op = reinterpret_cast<float4*>(out) + (size_t)tb * 32768;
        #pragma unroll
        for (int i = 0; i < 64; i++) op[tid + i*512] = z;
    }

    // staging geometry: thread loads float4 (4 k) for tokens s_tok0, s_tok0+64
    const int s_tok0 = tid >> 3;
    const int s_kq   = tid & 7;
    const float* sbase  = xblk + (size_t)s_tok0*DM + s_kq*4;
    const float* sbase2 = sbase + (size_t)64*DM;

    float4 r0, r1;
    r0 = *reinterpret_cast<const float4*>(sbase);
    r1 = *reinterpret_cast<const float4*>(sbase2);

    // load full controller into smem
    {
        const float4* cg4 = reinterpret_cast<const float4*>(ctrl);
        float4* cs4 = reinterpret_cast<float4*>(ctrl_s);
        #pragma unroll
        for (int i = 0; i < 16; i++) cs4[tid + i*512] = cg4[tid + i*512];
    }
    {
        const float* p0 = reinterpret_cast<const float*>(&r0);
        const float* p1 = reinterpret_cast<const float*>(&r1);
        #pragma unroll
        for (int j = 0; j < 4; j++) {
            xk0[(s_kq*4 + j)*XKROW_U + s_tok0]      = pack2(p0[j], p0[j]);
            xk0[(s_kq*4 + j)*XKROW_U + s_tok0 + 64] = pack2(p1[j], p1[j]);
        }
    }
    __syncthreads();

    ull acc[4][4];
    #pragma unroll
    for (int i = 0; i < 4; i++)
        #pragma unroll
        for (int p = 0; p < 4; p++) acc[i][p] = 0ull;

    for (int c = 0; c < 32; c++) {
        // issue next chunk's LDGs first
        if (c < 31) {
            r0 = *reinterpret_cast<const float4*>(sbase  + (c+1)*32);
            r1 = *reinterpret_cast<const float4*>(sbase2 + (c+1)*32);
        }

        // compute chunk c
        const ull* xb = (c & 1) ? xk1 : xk0;
        #pragma unroll
        for (int u = 0; u < 8; u++) {
            const ulonglong2* cb = reinterpret_cast<const ulonglong2*>(
                ctrl_s + (size_t)(c*32 + ks*8 + u)*16 + eq*4);
            ulonglong2 q0 = cb[0], q1 = cb[1];
            ull cu0 = q0.x, cu1 = q0.y, cu2 = q1.x, cu3 = q1.y;
            const ull* xrow = xb + (ks*8 + u)*XKROW_U + tg;
            #pragma unroll
            for (int i = 0; i < 4; i++) {
                ull x2 = xrow[32*i];
                ffma2(acc[i][0], x2, cu0);
                ffma2(acc[i][1], x2, cu1);
                ffma2(acc[i][2], x2, cu2);
                ffma2(acc[i][3], x2, cu3);
            }
        }

        // stage chunk c+1 (dup pairs)
        if (c < 31) {
            ull* bw = ((c+1) & 1) ? xk1 : xk0;
            const float* p0 = reinterpret_cast<const float*>(&r0);
            const float* p1 = reinterpret_cast<const float*>(&r1);
            #pragma unroll
            for (int j = 0; j < 4; j++) {
                bw[(s_kq*4 + j)*XKROW_U + s_tok0]      = pack2(p0[j], p0[j]);
                bw[(s_kq*4 + j)*XKROW_U + s_tok0 + 64] = pack2(p1[j], p1[j]);
            }
        }
        __syncthreads();
    }

    // reduce over 4 k-slices via smem (reuse ctrl_s)
    ull* red = ctrl_s;
    #pragma unroll
    for (int i = 0; i < 4; i++)
        #pragma unroll
        for (int p = 0; p < 4; p++)
            red[(((size_t)(eq*4 + ks)*128) + (tg + 32*i))*4 + p] = acc[i][p];
    __syncthreads();

    #pragma unroll
    for (int j = 0; j < 4; j++) {
        int s = tid*4 + j;               // item = (tok, expert-pair)
        int tok = s >> 4, pr = s & 15;
        int peq = pr >> 2, pp = pr & 3;
        float lo = 0.f, hi = 0.f;
        #pragma unroll
        for (int k2 = 0; k2 < 4; k2++) {
            float a, b;
            unpack2(red[(((size_t)(peq*4 + k2)*128) + tok)*4 + pp], a, b);
            lo += a; hi += b;
        }
        int gt = tb*128 + tok;
        int b  = gt >> 12;
        int sg = gt & 4095;
        int g  = sg >> 2, t = sg & 3;
        float tbk = (float)t * (1e-6f / 3.0f);   // linspace(0,1e-6,4)[t]
        int row = (b*4 + t)*32 + 2*pr;
        g_logitsT[(size_t)row*1024 + g]     = lo + tbk;
        g_logitsT[(size_t)(row+1)*1024 + g] = hi + tbk;
    }
}

// ---------------------------------------------------------------------------
// K_sel: one block per (b,t,e) row: argmax + softmax denominator over 1024 g.
// ---------------------------------------------------------------------------
__global__ void __launch_bounds__(256, 8)
k_sel()
{
    __shared__ float rm[8];
    __shared__ int   rmi[8];
    __shared__ float rs[8];
    __shared__ float mfin;

    const int tid  = threadIdx.x;
    const int lane = tid & 31;
    const int wp   = tid >> 5;
    const float* L = g_logitsT + ((size_t)blockIdx.x << 10);

    float m = -3.4e38f; int mi = 0;
    #pragma unroll
    for (int j = 0; j < 4; j++) {
        int i = tid + j*256;
        float v = L[i];
        if (v > m) { m = v; mi = i; }
    }
    #pragma unroll
    for (int o = 16; o; o >>= 1) {
        float om = __shfl_down_sync(0xffffffffu, m, o);
        int   oi = __shfl_down_sync(0xffffffffu, mi, o);
        if (om > m || (om == m && oi < mi)) { m = om; mi = oi; }
    }
    if (lane == 0) { rm[wp] = m; rmi[wp] = mi; }
    __syncthreads();
    if (tid == 0) {
        #pragma unroll
        for (int w = 1; w < 8; w++) {
            if (rm[w] > m || (rm[w] == m && rmi[w] < mi)) { m = rm[w]; mi = rmi[w]; }
        }
        g_selg[blockIdx.x] = mi;
        mfin = m;
    }
    __syncthreads();
    m = mfin;

    float s = 0.f;
    #pragma unroll
    for (int j = 0; j < 4; j++) s += expf(L[tid + j*256] - m);
    #pragma unroll
    for (int o = 16; o; o >>= 1) s += __shfl_down_sync(0xffffffffu, s, o);
    if (lane == 0) rs[wp] = s;
    __syncthreads();
    if (tid == 0) {
        float tot = 0.f;
        #pragma unroll
        for (int w = 0; w < 8; w++) tot += rs[w];
        g_selp[blockIdx.x] = 1.0f / tot;
    }
}

// ---------------------------------------------------------------------------
// K2: up-proj + down-proj + scatter-add, split over 2 f-halves.
// grid 256 = (b, e, fs) x 256 threads; 64 f per block.
// ---------------------------------------------------------------------------
__global__ void __launch_bounds__(256, 2)
k_expert(const float* __restrict__ x, const float* __restrict__ f1,
         const float* __restrict__ bias, const float* __restrict__ f2,
         float* __restrict__ out)
{
    __shared__ float xs[4][DM];          // 16KB
    __shared__ float part[8][4][64];     // 8KB
    __shared__ float avs[4][64];
    __shared__ float Wsm[4][64];
    __shared__ int   sg[4];
    __shared__ float sp[4];

    const int tid  = threadIdx.x;
    const int lane = tid & 31;
    const int b  = blockIdx.x >> 6;
    const int e  = (blockIdx.x >> 1) & 31;
    const int fs = blockIdx.x & 1;

    if (tid < 4) {
        sg[tid] = g_selg[(b*4 + tid)*32 + e];
        sp[tid] = g_selp[(b*4 + tid)*32 + e];
    }
    __syncthreads();

    // --- load the 4 selected token rows into smem ---
    {
        const int ts = tid >> 6;
        const int gt = tid & 63;
        const float* xr = x + ((size_t)b*SEQ + sg[ts]*4 + ts) * DM;
        float4* dst = reinterpret_cast<float4*>(xs[ts]);
        const float4* src = reinterpret_cast<const float4*>(xr);
        #pragma unroll
        for (int i = 0; i < 4; i++) dst[gt + i*64] = src[gt + i*64];
    }
    __syncthreads();

    // --- up-projection: warp w owns 128 d; lane handles f = lane, lane+32 ---
    {
        const int w = tid >> 5;
        float a0[4] = {0,0,0,0};    // f = fs*64 + lane
        float a1[4] = {0,0,0,0};    // f = fs*64 + lane + 32
        const float* f1p = f1 + (size_t)(w*128)*(NEXP*FE) + e*FE + fs*64 + lane;
        const float* x0 = xs[0] + w*128;
        const float* x1 = xs[1] + w*128;
        const float* x2 = xs[2] + w*128;
        const float* x3 = xs[3] + w*128;
        #pragma unroll 8
        for (int d = 0; d < 128; d++) {
            float w0 = f1p[(size_t)d * (NEXP*FE)];
            float w1 = f1p[(size_t)d * (NEXP*FE) + 32];
            float v0 = x0[d], v1 = x1[d], v2 = x2[d], v3 = x3[d];
            a0[0] += v0*w0; a0[1] += v1*w0; a0[2] += v2*w0; a0[3] += v3*w0;
            a1[0] += v0*w1; a1[1] += v1*w1; a1[2] += v2*w1; a1[3] += v3*w1;
        }
        #pragma unroll
        for (int t = 0; t < 4; t++) {
            part[w][t][lane]      = a0[t];
            part[w][t][lane + 32] = a1[t];
        }
    }
    __syncthreads();

    {
        const int t = tid >> 6, f = tid & 63;
        float s = 0.f;
        #pragma unroll
        for (int w = 0; w < 8; w++) s += part[w][t][f];
        avs[t][f] = s;
    }
    __syncthreads();

    if (tid < 64) {
        const int f = tid;
        float av[4] = {avs[0][f], avs[1][f], avs[2][f], avs[3][f]};
        int   gg[4] = {sg[0], sg[1], sg[2], sg[3]};
        float pp[4] = {sp[0], sp[1], sp[2], sp[3]};
        float bi = bias[e*FE + fs*64 + f];
        #pragma unroll
        for (int t = 0; t < 4; t++) {
            float sum = bi;
            #pragma unroll
            for (int t2 = 0; t2 < 4; t2++)
                if (gg[t2] == gg[t]) sum += pp[t2] * av[t2];
            Wsm[t][f] = pp[t] * fmaxf(sum, 0.f);
        }
    }
    __syncthreads();

    // --- down-projection: thread owns 4 d' columns, 64 f rows ---
    {
        float o0[4] = {0,0,0,0}, o1[4] = {0,0,0,0};
        float o2[4] = {0,0,0,0}, o3[4] = {0,0,0,0};
        const float* f2p = f2 + (size_t)e*FE*DM + (size_t)(fs*64)*DM + tid*4;
        #pragma unroll 8
        for (int f = 0; f < 64; f++) {
            float4 v = *reinterpret_cast<const float4*>(f2p + (size_t)f*DM);
            float w0 = Wsm[0][f], w1 = Wsm[1][f], w2 = Wsm[2][f], w3 = Wsm[3][f];
            o0[0] += w0*v.x; o0[1] += w0*v.y; o0[2] += w0*v.z; o0[3] += w0*v.w;
            o1[0] += w1*v.x; o1[1] += w1*v.y; o1[2] += w1*v.z; o1[3] += w1*v.w;
            o2[0] += w2*v.x; o2[1] += w2*v.y; o2[2] += w2*v.z; o2[3] += w2*v.w;
            o3[0] += w3*v.x; o3[1] += w3*v.y; o3[2] += w3*v.z; o3[3] += w3*v.w;
        }
        float* ob = out + (size_t)b*SEQ*DM + tid*4;
        float* r0 = ob + (size_t)(sg[0]*4 + 0)*DM;
        float* r1 = ob + (size_t)(sg[1]*4 + 1)*DM;
        float* r2 = ob + (size_t)(sg[2]*4 + 2)*DM;
        float* r3 = ob + (size_t)(sg[3]*4 + 3)*DM;
        #pragma unroll
        for (int j = 0; j < 4; j++) atomicAdd(r0 + j, o0[j]);
        #pragma unroll
        for (int j = 0; j < 4; j++) atomicAdd(r1 + j, o1[j]);
        #pragma unroll
        for (int j = 0; j < 4; j++) atomicAdd(r2 + j, o2[j]);
        #pragma unroll
        for (int j = 0; j < 4; j++) atomicAdd(r3 + j, o3[j]);
    }
}

extern "C" void kernel_launch(void* const* d_in, const int* in_sizes, int n_in,
                              void* d_out, int out_size)
{
    const float* x    = (const float*)d_in[0];
    const float* ctrl = (const float*)d_in[1];
    const float* f1   = (const float*)d_in[2];
    const float* bias = (const float*)d_in[3];
    const float* f2   = (const float*)d_in[4];
    float* out = (float*)d_out;

    cudaFuncSetAttribute(k_logits, cudaFuncAttributeMaxDynamicSharedMemorySize, SMEM1);

    k_logits<<<128, 512, SMEM1>>>(x, ctrl, out);
    k_sel<<<BATCH*TT*NEXP, 256>>>();
    k_expert<<<BATCH*NEXP*2, 256>>>(x, f1, bias, f2, out);
}

// round 10
// speedup vs baseline: 1.1835x; 1.0732x over previous
#include <cuda_runtime.h>
#include <cstdint>
#include <math.h>

#define DM   1024
#define NEXP 32
#define FE   128
#define TT   4
#define BATCH 4
#define SEQ  4096
#define NTOK (BATCH*SEQ)   // 16384
#define NGRP (SEQ/TT)      // 1024

typedef unsigned long long ull;

// scratch (device globals; no allocation)
__device__ float g_logitsT[BATCH*TT*NEXP*NGRP];   // 2MB [(b*4+t)*32+e][g]
__device__ int   g_selg[BATCH*TT*NEXP];
__device__ float g_selp[BATCH*TT*NEXP];

__device__ __forceinline__ ull pack2(float a, float b) {
    ull r; asm("mov.b64 %0,{%1,%2};" : "=l"(r) : "f"(a), "f"(b)); return r;
}
__device__ __forceinline__ void unpack2(ull v, float& a, float& b) {
    asm("mov.b64 {%0,%1},%2;" : "=f"(a), "=f"(b) : "l"(v));
}
__device__ __forceinline__ void ffma2(ull& d, ull a, ull b) {
    asm("fma.rn.f32x2 %0,%1,%2,%0;" : "+l"(d) : "l"(a), "l"(b));
}

// ---------------------------------------------------------------------------
// K1: zero output + logits GEMM. 256 blocks = 128 token-tiles x 2 expert
// halves, 256 threads, 2 blocks/SM (4 warps/SMSP). warp = (eq, ks):
// eq = expert octet within half, ks = k-slice. Thread tile: 4 tok x 8 exp.
// x staged transposed [k][tok] pad-129 (conflict-free STS/LDS, R7 layout).
// ctrl half (64KB) resident in smem.
// ---------------------------------------------------------------------------
#define XKROW 129
#define XKBUF (32*XKROW)                         // floats per buffer
#define SMEM1 (65536 + 2*XKBUF*4)                // 98560 -> 2 blocks/SM

__global__ void __launch_bounds__(256, 2)
k_logits(const float* __restrict__ x, const float* __restrict__ ctrl,
         float* __restrict__ out)
{
    extern __shared__ char smraw[];
    ull*   ctrl_s = reinterpret_cast<ull*>(smraw);              // [1024k][8 ull]
    float* xk0    = reinterpret_cast<float*>(smraw + 65536);    // [32][129]
    float* xk1    = xk0 + XKBUF;

    const int tid = threadIdx.x;
    const int tg  = tid & 31;
    const int w   = tid >> 5;
    const int eq  = w >> 2;          // expert octet within the half (0..1)
    const int ks  = w & 3;           // k slice (8 k of 32-k chunk)
    const int eh  = blockIdx.x & 1;  // expert half
    const int tb  = blockIdx.x >> 1; // token tile (128 tokens)
    const float* xblk = x + (size_t)tb * 128 * DM;

    // fire-and-forget zero of a 1/256 slab of out
    {
        float4 z = make_float4(0.f, 0.f, 0.f, 0.f);
        float4* op = reinterpret_cast<float4*>(out) + (size_t)blockIdx.x * 16384;
        #pragma unroll
        for (int i = 0; i < 64; i++) op[tid + i*256] = z;
    }

    // staging geometry: q = tid + i*256 (i<4); tok = q>>3, kq = q&7
    const int s_tok0 = tid >> 3;          // 0..31 base, tokens step by 32
    const int s_kq   = tid & 7;
    const float* sb0 = xblk + (size_t)s_tok0*DM + s_kq*4;

    float4 r[4];
    #pragma unroll
    for (int i = 0; i < 4; i++)
        r[i] = *reinterpret_cast<const float4*>(sb0 + (size_t)(i*32)*DM);

    // load controller half into smem: [k][16 floats] = [k][8 ull]
    {
        const float4* cg4 = reinterpret_cast<const float4*>(ctrl);
        float4* cs4 = reinterpret_cast<float4*>(ctrl_s);
        #pragma unroll
        for (int i = 0; i < 16; i++) {
            int q = tid + i*256;                  // 0..4095
            cs4[q] = cg4[(q >> 2)*8 + eh*4 + (q & 3)];
        }
    }
    {
        #pragma unroll
        for (int i = 0; i < 4; i++) {
            const float* p = reinterpret_cast<const float*>(&r[i]);
            #pragma unroll
            for (int j = 0; j < 4; j++)
                xk0[(s_kq*4 + j)*XKROW + s_tok0 + i*32] = p[j];
        }
    }
    __syncthreads();

    ull acc[4][4];
    #pragma unroll
    for (int i = 0; i < 4; i++)
        #pragma unroll
        for (int p = 0; p < 4; p++) acc[i][p] = 0ull;

    for (int c = 0; c < 32; c++) {
        // issue next chunk's LDGs first
        if (c < 31) {
            #pragma unroll
            for (int i = 0; i < 4; i++)
                r[i] = *reinterpret_cast<const float4*>(
                    sb0 + (size_t)(i*32)*DM + (c+1)*32);
        }

        // compute chunk c
        const float* xb = (c & 1) ? xk1 : xk0;
        #pragma unroll
        for (int u = 0; u < 8; u++) {
            const ulonglong2* cb = reinterpret_cast<const ulonglong2*>(
                ctrl_s + (size_t)(c*32 + ks*8 + u)*8 + eq*4);
            ulonglong2 q0 = cb[0], q1 = cb[1];
            ull cu0 = q0.x, cu1 = q0.y, cu2 = q1.x, cu3 = q1.y;
            const float* xrow = xb + (ks*8 + u)*XKROW + tg;
            #pragma unroll
            for (int i = 0; i < 4; i++) {
                float xf = xrow[32*i];
                ull x2 = pack2(xf, xf);
                ffma2(acc[i][0], x2, cu0);
                ffma2(acc[i][1], x2, cu1);
                ffma2(acc[i][2], x2, cu2);
                ffma2(acc[i][3], x2, cu3);
            }
        }

        // stage chunk c+1
        if (c < 31) {
            float* bw = ((c+1) & 1) ? xk1 : xk0;
            #pragma unroll
            for (int i = 0; i < 4; i++) {
                const float* p = reinterpret_cast<const float*>(&r[i]);
                #pragma unroll
                for (int j = 0; j < 4; j++)
                    bw[(s_kq*4 + j)*XKROW + s_tok0 + i*32] = p[j];
            }
        }
        __syncthreads();
    }

    // reduce over 4 k-slices via smem (reuse ctrl_s region)
    ull* red = ctrl_s;
    #pragma unroll
    for (int i = 0; i < 4; i++)
        #pragma unroll
        for (int p = 0; p < 4; p++)
            red[(((size_t)(eq*4 + ks)*128) + (tg + 32*i))*4 + p] = acc[i][p];
    __syncthreads();

    #pragma unroll
    for (int j = 0; j < 4; j++) {
        int s = tid*4 + j;               // item = (tok, pair-in-half), 0..1023
        int tok = s >> 3, pr = s & 7;    // pr: pair 0..7 within this half
        int peq = pr >> 2, pp = pr & 3;
        float lo = 0.f, hi = 0.f;
        #pragma unroll
        for (int k2 = 0; k2 < 4; k2++) {
            float a, b;
            unpack2(red[(((size_t)(peq*4 + k2)*128) + tok)*4 + pp], a, b);
            lo += a; hi += b;
        }
        int gt = tb*128 + tok;
        int b  = gt >> 12;
        int sg = gt & 4095;
        int g  = sg >> 2, t = sg & 3;
        float tbk = (float)t * (1e-6f / 3.0f);   // linspace(0,1e-6,4)[t]
        int row = (b*4 + t)*32 + eh*16 + 2*pr;
        g_logitsT[(size_t)row*1024 + g]     = lo + tbk;
        g_logitsT[(size_t)(row+1)*1024 + g] = hi + tbk;
    }
}

// ---------------------------------------------------------------------------
// K_sel: one block per (b,t,e) row: argmax + softmax denominator over 1024 g.
// ---------------------------------------------------------------------------
__global__ void __launch_bounds__(256, 8)
k_sel()
{
    __shared__ float rm[8];
    __shared__ int   rmi[8];
    __shared__ float rs[8];
    __shared__ float mfin;

    const int tid  = threadIdx.x;
    const int lane = tid & 31;
    const int wp   = tid >> 5;
    const float* L = g_logitsT + ((size_t)blockIdx.x << 10);

    float m = -3.4e38f; int mi = 0;
    #pragma unroll
    for (int j = 0; j < 4; j++) {
        int i = tid + j*256;
        float v = L[i];
        if (v > m) { m = v; mi = i; }
    }
    #pragma unroll
    for (int o = 16; o; o >>= 1) {
        float om = __shfl_down_sync(0xffffffffu, m, o);
        int   oi = __shfl_down_sync(0xffffffffu, mi, o);
        if (om > m || (om == m && oi < mi)) { m = om; mi = oi; }
    }
    if (lane == 0) { rm[wp] = m; rmi[wp] = mi; }
    __syncthreads();
    if (tid == 0) {
        #pragma unroll
        for (int w = 1; w < 8; w++) {
            if (rm[w] > m || (rm[w] == m && rmi[w] < mi)) { m = rm[w]; mi = rmi[w]; }
        }
        g_selg[blockIdx.x] = mi;
        mfin = m;
    }
    __syncthreads();
    m = mfin;

    float s = 0.f;
    #pragma unroll
    for (int j = 0; j < 4; j++) s += expf(L[tid + j*256] - m);
    #pragma unroll
    for (int o = 16; o; o >>= 1) s += __shfl_down_sync(0xffffffffu, s, o);
    if (lane == 0) rs[wp] = s;
    __syncthreads();
    if (tid == 0) {
        float tot = 0.f;
        #pragma unroll
        for (int w = 0; w < 8; w++) tot += rs[w];
        g_selp[blockIdx.x] = 1.0f / tot;
    }
}

// ---------------------------------------------------------------------------
// K2: up-proj + down-proj + scatter-add, split over 2 f-halves.
// grid 256 = (b, e, fs) x 256 threads; 64 f per block.
// ---------------------------------------------------------------------------
__global__ void __launch_bounds__(256, 2)
k_expert(const float* __restrict__ x, const float* __restrict__ f1,
         const float* __restrict__ bias, const float* __restrict__ f2,
         float* __restrict__ out)
{
    __shared__ float xs[4][DM];          // 16KB
    __shared__ float part[8][4][64];     // 8KB
    __shared__ float avs[4][64];
    __shared__ float Wsm[4][64];
    __shared__ int   sg[4];
    __shared__ float sp[4];

    const int tid  = threadIdx.x;
    const int lane = tid & 31;
    const int b  = blockIdx.x >> 6;
    const int e  = (blockIdx.x >> 1) & 31;
    const int fs = blockIdx.x & 1;

    if (tid < 4) {
        sg[tid] = g_selg[(b*4 + tid)*32 + e];
        sp[tid] = g_selp[(b*4 + tid)*32 + e];
    }
    __syncthreads();

    // --- load the 4 selected token rows into smem ---
    {
        const int ts = tid >> 6;
        const int gt = tid & 63;
        const float* xr = x + ((size_t)b*SEQ + sg[ts]*4 + ts) * DM;
        float4* dst = reinterpret_cast<float4*>(xs[ts]);
        const float4* src = reinterpret_cast<const float4*>(xr);
        #pragma unroll
        for (int i = 0; i < 4; i++) dst[gt + i*64] = src[gt + i*64];
    }
    __syncthreads();

    // --- up-projection: warp w owns 128 d; lane handles f = lane, lane+32 ---
    {
        const int w = tid >> 5;
        float a0[4] = {0,0,0,0};
        float a1[4] = {0,0,0,0};
        const float* f1p = f1 + (size_t)(w*128)*(NEXP*FE) + e*FE + fs*64 + lane;
        const float* x0 = xs[0] + w*128;
        const float* x1 = xs[1] + w*128;
        const float* x2 = xs[2] + w*128;
        const float* x3 = xs[3] + w*128;
        #pragma unroll 8
        for (int d = 0; d < 128; d++) {
            float w0 = f1p[(size_t)d * (NEXP*FE)];
            float w1 = f1p[(size_t)d * (NEXP*FE) + 32];
            float v0 = x0[d], v1 = x1[d], v2 = x2[d], v3 = x3[d];
            a0[0] += v0*w0; a0[1] += v1*w0; a0[2] += v2*w0; a0[3] += v3*w0;
            a1[0] += v0*w1; a1[1] += v1*w1; a1[2] += v2*w1; a1[3] += v3*w1;
        }
        #pragma unroll
        for (int t = 0; t < 4; t++) {
            part[w][t][lane]      = a0[t];
            part[w][t][lane + 32] = a1[t];
        }
    }
    __syncthreads();

    {
        const int t = tid >> 6, f = tid & 63;
        float s = 0.f;
        #pragma unroll
        for (int w = 0; w < 8; w++) s += part[w][t][f];
        avs[t][f] = s;
    }
    __syncthreads();

    if (tid < 64) {
        const int f = tid;
        float av[4] = {avs[0][f], avs[1][f], avs[2][f], avs[3][f]};
        int   gg[4] = {sg[0], sg[1], sg[2], sg[3]};
        float pp[4] = {sp[0], sp[1], sp[2], sp[3]};
        float bi = bias[e*FE + fs*64 + f];
        #pragma unroll
        for (int t = 0; t < 4; t++) {
            float sum = bi;
            #pragma unroll
            for (int t2 = 0; t2 < 4; t2++)
                if (gg[t2] == gg[t]) sum += pp[t2] * av[t2];
            Wsm[t][f] = pp[t] * fmaxf(sum, 0.f);
        }
    }
    __syncthreads();

    // --- down-projection: thread owns 4 d' columns, 64 f rows ---
    {
        float o0[4] = {0,0,0,0}, o1[4] = {0,0,0,0};
        float o2[4] = {0,0,0,0}, o3[4] = {0,0,0,0};
        const float* f2p = f2 + (size_t)e*FE*DM + (size_t)(fs*64)*DM + tid*4;
        #pragma unroll 8
        for (int f = 0; f < 64; f++) {
            float4 v = *reinterpret_cast<const float4*>(f2p + (size_t)f*DM);
            float w0 = Wsm[0][f], w1 = Wsm[1][f], w2 = Wsm[2][f], w3 = Wsm[3][f];
            o0[0] += w0*v.x; o0[1] += w0*v.y; o0[2] += w0*v.z; o0[3] += w0*v.w;
            o1[0] += w1*v.x; o1[1] += w1*v.y; o1[2] += w1*v.z; o1[3] += w1*v.w;
            o2[0] += w2*v.x; o2[1] += w2*v.y; o2[2] += w2*v.z; o2[3] += w2*v.w;
            o3[0] += w3*v.x; o3[1] += w3*v.y; o3[2] += w3*v.z; o3[3] += w3*v.w;
        }
        float* ob = out + (size_t)b*SEQ*DM + tid*4;
        float* r0 = ob + (size_t)(sg[0]*4 + 0)*DM;
        float* r1 = ob + (size_t)(sg[1]*4 + 1)*DM;
        float* r2 = ob + (size_t)(sg[2]*4 + 2)*DM;
        float* r3 = ob + (size_t)(sg[3]*4 + 3)*DM;
        #pragma unroll
        for (int j = 0; j < 4; j++) atomicAdd(r0 + j, o0[j]);
        #pragma unroll
        for (int j = 0; j < 4; j++) atomicAdd(r1 + j, o1[j]);
        #pragma unroll
        for (int j = 0; j < 4; j++) atomicAdd(r2 + j, o2[j]);
        #pragma unroll
        for (int j = 0; j < 4; j++) atomicAdd(r3 + j, o3[j]);
    }
}

extern "C" void kernel_launch(void* const* d_in, const int* in_sizes, int n_in,
                              void* d_out, int out_size)
{
    const float* x    = (const float*)d_in[0];
    const float* ctrl = (const float*)d_in[1];
    const float* f1   = (const float*)d_in[2];
    const float* bias = (const float*)d_in[3];
    const float* f2   = (const float*)d_in[4];
    float* out = (float*)d_out;

    cudaFuncSetAttribute(k_logits, cudaFuncAttributeMaxDynamicSharedMemorySize, SMEM1);

    k_logits<<<256, 256, SMEM1>>>(x, ctrl, out);
    k_sel<<<BATCH*TT*NEXP, 256>>>();
    k_expert<<<BATCH*NEXP*2, 256>>>(x, f1, bias, f2, out);
}